// round 2
// baseline (speedup 1.0000x reference)
#include <cuda_runtime.h>
#include <cstdint>

// DETRMatcher: all the softmax/cdist/argmin machinery in the reference is dead
// code w.r.t. the returned tensors:
//   matched_indices = zeros.at[b, rows].set(0)  -> all zeros
//   tgt_idx         = zeros.at[b, rows].set(0)  -> all zeros
//   out_bbox        = outputs_coord (reshape)   -> straight copy
//   tgt_bbox        = target_boxes              -> straight copy
//
// JAX default config has x64 DISABLED, so the "int64" tensors are int32 and
// the concatenated output promotes to float32 (8,100,000 f32 elements):
//   [0, 1.62M)        : 0.0f           (two int zero tensors, 810000 each)
//   [1.62M, 4.86M)    : outputs_coord  (3.24M f32, bitwise copy)
//   [4.86M, 8.10M)    : target_boxes   (3.24M f32, bitwise copy)

static constexpr long long N_ZERO  = 2LL * 900 * 900;        // 1,620,000
static constexpr long long N_COORD = 900LL * 900 * 4;        // 3,240,000

static constexpr long long V_ZERO  = N_ZERO / 4;             // 405,000 float4 slots
static constexpr long long V_COORD = N_COORD / 4;            // 810,000
static constexpr long long V_TOTAL = V_ZERO + 2 * V_COORD;   // 2,025,000

__global__ void detr_matcher_pack_f32(const float4* __restrict__ coord,
                                      const float4* __restrict__ boxes,
                                      float4* __restrict__ out)
{
    long long j = (long long)blockIdx.x * blockDim.x + threadIdx.x;
    if (j >= V_TOTAL) return;

    float4 v;
    if (j < V_ZERO) {
        v.x = 0.0f; v.y = 0.0f; v.z = 0.0f; v.w = 0.0f;
    } else if (j < V_ZERO + V_COORD) {
        v = coord[j - V_ZERO];
    } else {
        v = boxes[j - (V_ZERO + V_COORD)];
    }
    out[j] = v;
}

extern "C" void kernel_launch(void* const* d_in, const int* in_sizes, int n_in,
                              void* d_out, int out_size)
{
    // metadata order: outputs_class [74.52M f32], outputs_coord [3.24M f32],
    //                 target_classes [900 int], target_boxes [3.24M f32]
    const float4* coord = (const float4*)d_in[1];
    const float4* boxes = (const float4*)d_in[3];
    float4* out = (float4*)d_out;

    const int threads = 256;
    const int blocks = (int)((V_TOTAL + threads - 1) / threads);
    detr_matcher_pack_f32<<<blocks, threads>>>(coord, boxes, out);
}